// round 1
// baseline (speedup 1.0000x reference)
#include <cuda_runtime.h>
#include <math.h>
#include <stdint.h>

// Problem constants (fixed shapes from reference)
#define N_TOK 8192
#define DIM   512
#define FDIM  2048
#define NEXP  8
#define NASS  (N_TOK * 2)

#define EPS_F 2.220446049250313e-16f

// -------- scratch (static device globals; no runtime allocation) --------
__device__ float g_H[(size_t)NASS * FDIM];   // 128 MB: relu(x@W1+b1) per assignment
__device__ float g_O[(size_t)NASS * DIM];    // 32 MB:  gate*exp(h@W2+b2) per assignment
__device__ int   g_cnt[NEXP];
__device__ int   g_off[NEXP];
__device__ int   g_cursor[NEXP];
__device__ int   g_tok_e[N_TOK * 2];         // per-token top-2 expert ids
__device__ float g_tok_g[N_TOK * 2];         // per-token top-2 gates
__device__ int   g_row_tok[NASS];            // assignment row -> token
__device__ float g_row_gate[NASS];           // assignment row -> gate
__device__ int   g_ass_row[N_TOK * 2];       // token,k -> assignment row

// ---------------------------------------------------------------
__global__ void zero_kernel() {
    int t = threadIdx.x;
    if (t < NEXP) { g_cnt[t] = 0; }
}

// gating: one warp per token. logits = x @ Wg, top-2, softmax over top-2.
__global__ void gate_kernel(const float* __restrict__ x, const float* __restrict__ Wg) {
    __shared__ float WgS[NEXP][DIM];
    int tid = threadIdx.x;
    for (int i = tid; i < DIM * NEXP; i += 256) {
        int d = i >> 3, e = i & 7;
        WgS[e][d] = Wg[i];
    }
    __syncthreads();

    int warp = tid >> 5, lane = tid & 31;
    int t = blockIdx.x * 8 + warp;

    float acc[NEXP];
#pragma unroll
    for (int e = 0; e < NEXP; e++) acc[e] = 0.f;

    const float* xr = x + (size_t)t * DIM;
    for (int j = lane; j < DIM; j += 32) {
        float xv = xr[j];
#pragma unroll
        for (int e = 0; e < NEXP; e++) acc[e] += xv * WgS[e][j];
    }
#pragma unroll
    for (int e = 0; e < NEXP; e++) {
#pragma unroll
        for (int o = 16; o > 0; o >>= 1)
            acc[e] += __shfl_xor_sync(0xffffffffu, acc[e], o);
    }

    if (lane == 0) {
        float best = -INFINITY, sec = -INFINITY;
        int bi = 0, si = 0;
#pragma unroll
        for (int e = 0; e < NEXP; e++) {
            float v = acc[e];
            if (v > best)     { sec = best; si = bi; best = v; bi = e; }
            else if (v > sec) { sec = v; si = e; }
        }
        // softmax over (best, sec); max subtraction like jax
        float e1 = expf(sec - best);
        float s  = 1.f + e1;
        float gb = 1.f / s, gs = e1 / s;
        g_tok_e[2 * t]     = bi;  g_tok_e[2 * t + 1] = si;
        g_tok_g[2 * t]     = gb;  g_tok_g[2 * t + 1] = gs;
        atomicAdd(&g_cnt[bi], 1);
        atomicAdd(&g_cnt[si], 1);
    }
}

__global__ void prefix_kernel() {
    int o = 0;
    for (int e = 0; e < NEXP; e++) {
        g_off[e] = o;
        g_cursor[e] = o;
        o += g_cnt[e];
    }
}

__global__ void assign_kernel() {
    int t = blockIdx.x * 256 + threadIdx.x;  // 32 x 256 = 8192
    int e0 = g_tok_e[2 * t], e1 = g_tok_e[2 * t + 1];
    int r0 = atomicAdd(&g_cursor[e0], 1);
    int r1 = atomicAdd(&g_cursor[e1], 1);
    g_row_tok[r0]  = t; g_row_gate[r0] = g_tok_g[2 * t];
    g_row_tok[r1]  = t; g_row_gate[r1] = g_tok_g[2 * t + 1];
    g_ass_row[2 * t]     = r0;
    g_ass_row[2 * t + 1] = r1;
}

// ---------------------------------------------------------------
// SGEMM1: H[r, :] = relu( x[tok(r), :] @ W1[e] + b1[e] )
// grid: (FDIM/128, 64, NEXP), block 256, 128x128 tile, 8x8 microkernel, K-tile 16
__global__ __launch_bounds__(256) void gemm1_kernel(
    const float* __restrict__ x, const float* __restrict__ W1,
    const float* __restrict__ b1)
{
    int e   = blockIdx.z;
    int cnt = g_cnt[e];
    int m0  = blockIdx.y * 128;
    if (m0 >= cnt) return;
    int base = g_off[e];
    int n0   = blockIdx.x * 128;
    const float* B = W1 + (size_t)e * DIM * FDIM;   // [512][2048] row-major

    __shared__ float As[16][128];
    __shared__ float Bs[16][128];

    int tid = threadIdx.x;
    // A tile load map: am = row within tile, akh = k-half (0 or 8)
    int am  = tid & 127;
    int akh = (tid >> 7) * 8;
    int avalid = (m0 + am) < cnt;
    int tok = avalid ? g_row_tok[base + m0 + am] : 0;
    const float* aptr = x + (size_t)tok * DIM + akh;
    // B tile load map
    int bk = tid >> 4;
    int bn = (tid & 15) * 8;
    const float* bptr = B + (size_t)bk * FDIM + n0 + bn;

    int tx = tid & 15, ty = tid >> 4;

    float c[8][8];
#pragma unroll
    for (int i = 0; i < 8; i++)
#pragma unroll
        for (int j = 0; j < 8; j++) c[i][j] = 0.f;

    for (int kt = 0; kt < DIM; kt += 16) {
        float4 a0 = *(const float4*)(aptr + kt);
        float4 a1 = *(const float4*)(aptr + kt + 4);
        float4 bv0 = *(const float4*)(bptr + (size_t)kt * FDIM);
        float4 bv1 = *(const float4*)(bptr + (size_t)kt * FDIM + 4);
        __syncthreads();
        As[akh + 0][am] = a0.x; As[akh + 1][am] = a0.y;
        As[akh + 2][am] = a0.z; As[akh + 3][am] = a0.w;
        As[akh + 4][am] = a1.x; As[akh + 5][am] = a1.y;
        As[akh + 6][am] = a1.z; As[akh + 7][am] = a1.w;
        *(float4*)&Bs[bk][bn]     = bv0;
        *(float4*)&Bs[bk][bn + 4] = bv1;
        __syncthreads();
#pragma unroll
        for (int kk = 0; kk < 16; kk++) {
            float a[8], b[8];
            *(float4*)&a[0] = *(const float4*)&As[kk][ty * 8];
            *(float4*)&a[4] = *(const float4*)&As[kk][ty * 8 + 4];
            *(float4*)&b[0] = *(const float4*)&Bs[kk][tx * 8];
            *(float4*)&b[4] = *(const float4*)&Bs[kk][tx * 8 + 4];
#pragma unroll
            for (int i = 0; i < 8; i++)
#pragma unroll
                for (int j = 0; j < 8; j++) c[i][j] += a[i] * b[j];
        }
    }

    // epilogue: + b1, relu, store to H
#pragma unroll
    for (int i = 0; i < 8; i++) {
        int m = m0 + ty * 8 + i;
        if (m < cnt) {
            float* hrow = g_H + (size_t)(base + m) * FDIM + n0 + tx * 8;
            const float* brow = b1 + (size_t)e * FDIM + n0 + tx * 8;
#pragma unroll
            for (int j = 0; j < 8; j++) {
                float v = c[i][j] + brow[j];
                hrow[j] = v > 0.f ? v : 0.f;
            }
        }
    }
}

// ---------------------------------------------------------------
// SGEMM2: O[r, :] = gate(r) * exp( H[r, :] @ W2[e] + b2[e] )
// grid: (DIM/128, 64, NEXP)
__global__ __launch_bounds__(256) void gemm2_kernel(
    const float* __restrict__ W2, const float* __restrict__ b2)
{
    int e   = blockIdx.z;
    int cnt = g_cnt[e];
    int m0  = blockIdx.y * 128;
    if (m0 >= cnt) return;
    int base = g_off[e];
    int n0   = blockIdx.x * 128;
    const float* B = W2 + (size_t)e * FDIM * DIM;   // [2048][512] row-major

    __shared__ float As[16][128];
    __shared__ float Bs[16][128];

    int tid = threadIdx.x;
    int am  = tid & 127;
    int akh = (tid >> 7) * 8;
    int avalid = (m0 + am) < cnt;
    int arow = base + m0 + (avalid ? am : 0);
    const float* aptr = g_H + (size_t)arow * FDIM + akh;

    int bk = tid >> 4;
    int bn = (tid & 15) * 8;
    const float* bptr = B + (size_t)bk * DIM + n0 + bn;

    int tx = tid & 15, ty = tid >> 4;

    float c[8][8];
#pragma unroll
    for (int i = 0; i < 8; i++)
#pragma unroll
        for (int j = 0; j < 8; j++) c[i][j] = 0.f;

    for (int kt = 0; kt < FDIM; kt += 16) {
        float4 a0 = *(const float4*)(aptr + kt);
        float4 a1 = *(const float4*)(aptr + kt + 4);
        float4 bv0 = *(const float4*)(bptr + (size_t)kt * DIM);
        float4 bv1 = *(const float4*)(bptr + (size_t)kt * DIM + 4);
        __syncthreads();
        As[akh + 0][am] = a0.x; As[akh + 1][am] = a0.y;
        As[akh + 2][am] = a0.z; As[akh + 3][am] = a0.w;
        As[akh + 4][am] = a1.x; As[akh + 5][am] = a1.y;
        As[akh + 6][am] = a1.z; As[akh + 7][am] = a1.w;
        *(float4*)&Bs[bk][bn]     = bv0;
        *(float4*)&Bs[bk][bn + 4] = bv1;
        __syncthreads();
#pragma unroll
        for (int kk = 0; kk < 16; kk++) {
            float a[8], b[8];
            *(float4*)&a[0] = *(const float4*)&As[kk][ty * 8];
            *(float4*)&a[4] = *(const float4*)&As[kk][ty * 8 + 4];
            *(float4*)&b[0] = *(const float4*)&Bs[kk][tx * 8];
            *(float4*)&b[4] = *(const float4*)&Bs[kk][tx * 8 + 4];
#pragma unroll
            for (int i = 0; i < 8; i++)
#pragma unroll
                for (int j = 0; j < 8; j++) c[i][j] += a[i] * b[j];
        }
    }

#pragma unroll
    for (int i = 0; i < 8; i++) {
        int m = m0 + ty * 8 + i;
        if (m < cnt) {
            int r = base + m;
            float gate = g_row_gate[r];
            float* orow = g_O + (size_t)r * DIM + n0 + tx * 8;
            const float* brow = b2 + (size_t)e * DIM + n0 + tx * 8;
#pragma unroll
            for (int j = 0; j < 8; j++) {
                float v = c[i][j] + brow[j];
                orow[j] = gate * expf(v);
            }
        }
    }
}

// ---------------------------------------------------------------
// combine: out[t,d] = log( O[r0(t),d] + O[r1(t),d] ), eps floor
__global__ void combine_kernel(float* __restrict__ out) {
    int i = blockIdx.x * 1024 + threadIdx.x;   // exactly N_TOK*DIM = 4096*1024
    int t = i >> 9;
    int d = i & (DIM - 1);
    int r0 = g_ass_row[2 * t];
    int r1 = g_ass_row[2 * t + 1];
    float s = g_O[(size_t)r0 * DIM + d] + g_O[(size_t)r1 * DIM + d];
    out[i] = logf(s == 0.f ? EPS_F : s);
}

// ---------------------------------------------------------------
extern "C" void kernel_launch(void* const* d_in, const int* in_sizes, int n_in,
                              void* d_out, int out_size) {
    const float* x  = (const float*)d_in[0];
    const float* Wg = (const float*)d_in[1];
    const float* W1 = (const float*)d_in[2];
    const float* b1 = (const float*)d_in[3];
    const float* W2 = (const float*)d_in[4];
    const float* b2 = (const float*)d_in[5];
    float* out = (float*)d_out;

    zero_kernel<<<1, 32>>>();
    gate_kernel<<<N_TOK / 8, 256>>>(x, Wg);
    prefix_kernel<<<1, 1>>>();
    assign_kernel<<<N_TOK / 256, 256>>>();
    gemm1_kernel<<<dim3(FDIM / 128, 64, NEXP), 256>>>(x, W1, b1);
    gemm2_kernel<<<dim3(DIM / 128, 64, NEXP), 256>>>(W2, b2);
    combine_kernel<<<(N_TOK * DIM) / 1024, 1024>>>(out);
}

// round 6
// speedup vs baseline: 3.3222x; 3.3222x over previous
#include <cuda_runtime.h>
#include <cuda_fp16.h>
#include <mma.h>
#include <math.h>
#include <stdint.h>

using namespace nvcuda;

// Problem constants
#define N_TOK 8192
#define DIM   512
#define FDIM  2048
#define NEXP  8
#define NASS  (N_TOK * 2)
#define EPS_F 2.220446049250313e-16f

// ---------------- scratch (static device globals; same set as passing R1 + nothing new) ----------------
__device__ float g_H[(size_t)NASS * FDIM];   // relu(x@W1+b1), fp32 (exactly like R1)
__device__ float g_O[(size_t)NASS * DIM];    // gate*exp(h@W2+b2), fp32
__device__ int   g_cnt[NEXP];
__device__ int   g_off[NEXP];
__device__ int   g_cursor[NEXP];
__device__ int   g_tok_e[N_TOK * 2];
__device__ float g_tok_g[N_TOK * 2];
__device__ int   g_row_tok[NASS];
__device__ float g_row_gate[NASS];
__device__ int   g_ass_row[N_TOK * 2];

// ---------------- gating / routing (R1-validated, unchanged) ----------------
__global__ void zero_kernel() {
    int t = threadIdx.x;
    if (t < NEXP) g_cnt[t] = 0;
}

__global__ void gate_kernel(const float* __restrict__ x, const float* __restrict__ Wg) {
    __shared__ float WgS[NEXP][DIM];
    int tid = threadIdx.x;
    for (int i = tid; i < DIM * NEXP; i += 256) {
        int d = i >> 3, e = i & 7;
        WgS[e][d] = Wg[i];
    }
    __syncthreads();
    int warp = tid >> 5, lane = tid & 31;
    int t = blockIdx.x * 8 + warp;
    float acc[NEXP];
#pragma unroll
    for (int e = 0; e < NEXP; e++) acc[e] = 0.f;
    const float* xr = x + (size_t)t * DIM;
    for (int j = lane; j < DIM; j += 32) {
        float xv = xr[j];
#pragma unroll
        for (int e = 0; e < NEXP; e++) acc[e] += xv * WgS[e][j];
    }
#pragma unroll
    for (int e = 0; e < NEXP; e++) {
#pragma unroll
        for (int o = 16; o > 0; o >>= 1) acc[e] += __shfl_xor_sync(0xffffffffu, acc[e], o);
    }
    if (lane == 0) {
        float best = -INFINITY, sec = -INFINITY;
        int bi = 0, si = 0;
#pragma unroll
        for (int e = 0; e < NEXP; e++) {
            float v = acc[e];
            if (v > best)     { sec = best; si = bi; best = v; bi = e; }
            else if (v > sec) { sec = v; si = e; }
        }
        float e1 = expf(sec - best);
        float s  = 1.f + e1;
        g_tok_e[2 * t] = bi;  g_tok_e[2 * t + 1] = si;
        g_tok_g[2 * t] = 1.f / s;  g_tok_g[2 * t + 1] = e1 / s;
        atomicAdd(&g_cnt[bi], 1);
        atomicAdd(&g_cnt[si], 1);
    }
}

__global__ void prefix_kernel() {
    int o = 0;
    for (int e = 0; e < NEXP; e++) { g_off[e] = o; g_cursor[e] = o; o += g_cnt[e]; }
}

__global__ void assign_kernel() {
    int t = blockIdx.x * 256 + threadIdx.x;
    int e0 = g_tok_e[2 * t], e1 = g_tok_e[2 * t + 1];
    int r0 = atomicAdd(&g_cursor[e0], 1);
    int r1 = atomicAdd(&g_cursor[e1], 1);
    g_row_tok[r0] = t; g_row_gate[r0] = g_tok_g[2 * t];
    g_row_tok[r1] = t; g_row_gate[r1] = g_tok_g[2 * t + 1];
    g_ass_row[2 * t] = r0;
    g_ass_row[2 * t + 1] = r1;
}

// ---------------- WMMA fp16 GEMM with R1 data flow (no staging; fp32 global -> half in smem) ----------------
// C[m][n] = sum_k A[m][k]*B[k][n].
// G1: A[m][k] = x[g_row_tok[base+m]][k] (fp32), B = W1[e] [D][F] row-major (fp32). H fp32 out.
// G2: A[m][k] = g_H[base+m][k] (fp32),          B = W2[e] [F][D] row-major (fp32). O fp32 out.
// CTA tile 128x128, KC=32, double-buffered static smem; 8 warps = 4(M) x 2(N), warp tile 32x64.
template<bool G1>
__global__ void moe_gemm_wmma(const float* __restrict__ x,
                              const float* __restrict__ W,
                              const float* __restrict__ bias) {
    constexpr int K    = G1 ? DIM : FDIM;
    constexpr int NOUT = G1 ? FDIM : DIM;
    constexpr int KT   = K / 32;

    __shared__ __align__(32) __half As[2][128 * 40];   // ldm 40
    __shared__ __align__(32) __half Bs[2][32 * 136];   // ldm 136
    __shared__ __align__(32) float  scr[8][16 * 16];

    int e   = blockIdx.z;
    int cnt = g_cnt[e];
    int m0  = blockIdx.y * 128;
    if (m0 >= cnt) return;
    int base = g_off[e];
    int n0   = blockIdx.x * 128;

    const float* Bb = W + (size_t)e * ((size_t)DIM * FDIM);

    int tid = threadIdx.x, wid = tid >> 5, lane = tid & 31;
    int wm = (wid & 3) * 32;
    int wn = (wid >> 2) * 64;

    // A row this thread loads: 2 rows per thread per stage (128 rows, 8 float4-chunks each -> 1024 chunks)
    // chunk ch: arow = ch>>3, ac = ch&7 (k offset ac*4)
    int tok[4];   // gathered source row index for the A chunks (per q)
#pragma unroll
    for (int q = 0; q < 4; q++) {
        int ch = q * 256 + tid;
        int arow = ch >> 3;
        int mr = m0 + arow; if (mr >= cnt) mr = cnt - 1;
        tok[q] = G1 ? g_row_tok[base + mr] : (base + mr);
    }

    float4 ra[4], rb[4];
    auto gload = [&](int kt) {
#pragma unroll
        for (int q = 0; q < 4; q++) {
            int ch = q * 256 + tid;
            int ac = ch & 7;                    // A: k chunk (4 floats)
            const float* arow_p = G1 ? (x + (size_t)tok[q] * DIM)
                                     : (g_H + (size_t)tok[q] * FDIM);
            ra[q] = *(const float4*)(arow_p + kt * 32 + ac * 4);
            int brow = ch >> 5, bc = ch & 31;   // B: 32 k-rows x 32 float4-chunks
            rb[q] = *(const float4*)(Bb + (size_t)(kt * 32 + brow) * NOUT + n0 + bc * 4);
        }
    };
    auto sstore = [&](int s) {
#pragma unroll
        for (int q = 0; q < 4; q++) {
            int ch = q * 256 + tid;
            int arow = ch >> 3, ac = ch & 7;
            __half2* ap = (__half2*)&As[s][arow * 40 + ac * 4];
            ap[0] = __floats2half2_rn(ra[q].x, ra[q].y);
            ap[1] = __floats2half2_rn(ra[q].z, ra[q].w);
            int brow = ch >> 5, bc = ch & 31;
            __half2* bp = (__half2*)&Bs[s][brow * 136 + bc * 4];
            bp[0] = __floats2half2_rn(rb[q].x, rb[q].y);
            bp[1] = __floats2half2_rn(rb[q].z, rb[q].w);
        }
    };

    wmma::fragment<wmma::accumulator, 16, 16, 16, float> acc[2][4];
#pragma unroll
    for (int mi = 0; mi < 2; mi++)
#pragma unroll
        for (int nj = 0; nj < 4; nj++) wmma::fill_fragment(acc[mi][nj], 0.f);

    gload(0);

#pragma unroll 1
    for (int kt = 0; kt < KT; kt++) {
        int s = kt & 1;
        __syncthreads();
        sstore(s);
        __syncthreads();
        if (kt + 1 < KT) gload(kt + 1);

#pragma unroll
        for (int kk = 0; kk < 2; kk++) {
            wmma::fragment<wmma::matrix_a, 16, 16, 16, __half, wmma::row_major> af[2];
            wmma::fragment<wmma::matrix_b, 16, 16, 16, __half, wmma::row_major> bf[4];
#pragma unroll
            for (int mi = 0; mi < 2; mi++)
                wmma::load_matrix_sync(af[mi], &As[s][(wm + mi * 16) * 40 + kk * 16], 40);
#pragma unroll
            for (int nj = 0; nj < 4; nj++)
                wmma::load_matrix_sync(bf[nj], &Bs[s][(kk * 16) * 136 + wn + nj * 16], 136);
#pragma unroll
            for (int mi = 0; mi < 2; mi++)
#pragma unroll
                for (int nj = 0; nj < 4; nj++)
                    wmma::mma_sync(acc[mi][nj], af[mi], bf[nj], acc[mi][nj]);
        }
    }

    // ---------------- epilogue via per-warp smem scratch ----------------
    __syncthreads();
    const float* be = bias + (size_t)e * NOUT + n0;
#pragma unroll
    for (int mi = 0; mi < 2; mi++) {
#pragma unroll
        for (int nj = 0; nj < 4; nj++) {
            wmma::store_matrix_sync(&scr[wid][0], acc[mi][nj], 16, wmma::mem_row_major);
            __syncwarp();
            int mbase = m0 + wm + mi * 16;
#pragma unroll
            for (int q = 0; q < 8; q++) {
                int idx = q * 32 + lane;
                int rr = idx >> 4, cc = idx & 15;
                int m = mbase + rr;
                if (m < cnt) {
                    int r = base + m;
                    int nc = wn + nj * 16 + cc;
                    float v = scr[wid][idx] + be[nc];
                    if (G1) {
                        g_H[(size_t)r * FDIM + n0 + nc] = v > 0.f ? v : 0.f;
                    } else {
                        g_O[(size_t)r * DIM + n0 + nc] = g_row_gate[r] * __expf(v);
                    }
                }
            }
            __syncwarp();
        }
    }
}

// ---------------- combine (R1-validated) ----------------
__global__ void combine_kernel(float* __restrict__ out) {
    int i = blockIdx.x * 1024 + threadIdx.x;
    int t = i >> 9;
    int d = i & (DIM - 1);
    int r0 = g_ass_row[2 * t];
    int r1 = g_ass_row[2 * t + 1];
    float s = g_O[(size_t)r0 * DIM + d] + g_O[(size_t)r1 * DIM + d];
    out[i] = logf(s == 0.f ? EPS_F : s);
}

// ---------------- launch ----------------
extern "C" void kernel_launch(void* const* d_in, const int* in_sizes, int n_in,
                              void* d_out, int out_size) {
    const float* x  = (const float*)d_in[0];
    const float* Wg = (const float*)d_in[1];
    const float* W1 = (const float*)d_in[2];
    const float* b1 = (const float*)d_in[3];
    const float* W2 = (const float*)d_in[4];
    const float* b2 = (const float*)d_in[5];
    float* out = (float*)d_out;

    zero_kernel<<<1, 32>>>();
    gate_kernel<<<N_TOK / 8, 256>>>(x, Wg);
    prefix_kernel<<<1, 1>>>();
    assign_kernel<<<N_TOK / 256, 256>>>();

    moe_gemm_wmma<true ><<<dim3(FDIM / 128, 64, NEXP), 256>>>(x, W1, b1);
    moe_gemm_wmma<false><<<dim3(DIM  / 128, 64, NEXP), 256>>>(x, W2, b2);

    combine_kernel<<<(N_TOK * DIM) / 1024, 1024>>>(out);
}